// round 1
// baseline (speedup 1.0000x reference)
#include <cuda_runtime.h>
#include <cuda_bf16.h>

// Problem constants
#define N_ROWS 8192
#define DIMK   1024
#define HALF_N 4096
#define INV_T  (1.0f / 0.07f)

// Scratch (allocation-free rule: __device__ globals)
__device__ float g_f[N_ROWS * DIMK];    // normalized features, 32 MB (L2-resident)
__device__ float g_sumexp[N_ROWS];      // per-row sum of exp(sim) excluding diagonal

// ---------------------------------------------------------------------------
// packed fp32x2 helpers (sm_100+): 2x FLOP per issue slot vs scalar FFMA
// ---------------------------------------------------------------------------
__device__ __forceinline__ unsigned long long pack2(float x, float y) {
    unsigned long long r;
    asm("mov.b64 %0, {%1, %2};" : "=l"(r) : "f"(x), "f"(y));
    return r;
}
__device__ __forceinline__ void unpack2(unsigned long long v, float& x, float& y) {
    asm("mov.b64 {%0, %1}, %2;" : "=f"(x), "=f"(y) : "l"(v));
}
__device__ __forceinline__ void fma2(unsigned long long& d,
                                     unsigned long long a,
                                     unsigned long long b) {
    asm("fma.rn.f32x2 %0, %1, %2, %3;" : "=l"(d) : "l"(a), "l"(b), "l"(d));
}

// ---------------------------------------------------------------------------
// Kernel A: L2-normalize rows of the input into g_f; zero accumulators.
// One block per row, 256 threads, 4 floats (1 float4) per thread.
// ---------------------------------------------------------------------------
__global__ void norm_kernel(const float* __restrict__ in, float* __restrict__ out) {
    int r = blockIdx.x;
    int t = threadIdx.x;
    const float4* src = reinterpret_cast<const float4*>(in + (size_t)r * DIMK);
    float4 v = src[t];
    float ss = v.x * v.x + v.y * v.y + v.z * v.z + v.w * v.w;
    #pragma unroll
    for (int m = 16; m; m >>= 1) ss += __shfl_xor_sync(0xffffffffu, ss, m);

    __shared__ float warpsum[8];
    if ((t & 31) == 0) warpsum[t >> 5] = ss;
    __syncthreads();
    __shared__ float s_inv;
    if (t == 0) {
        float s = 0.f;
        #pragma unroll
        for (int i = 0; i < 8; i++) s += warpsum[i];
        s_inv = 1.0f / sqrtf(s);
    }
    __syncthreads();
    float inv = s_inv;
    float4 o = make_float4(v.x * inv, v.y * inv, v.z * inv, v.w * inv);
    reinterpret_cast<float4*>(g_f + (size_t)r * DIMK)[t] = o;

    if (t == 0) g_sumexp[r] = 0.0f;
    if (r == 0 && t == 0) out[0] = 0.0f;   // d_out is poisoned; zero before atomics
}

// ---------------------------------------------------------------------------
// Kernel B: tiled sim-tile GEMM (128x128 per CTA over K=1024) with fused
// exp + diagonal mask + per-row partial-sum epilogue.
// 256 threads = 16x16, each thread owns an 8x8 micro-tile:
//   rows  = rowBase + ty*8 + i           (i = 0..7, contiguous)
//   cols  = colBase + tx + j*16          (j = 0..7, strided -> conflict-free LDS)
// Accumulate in packed f32x2 (4 col-pairs per row).
// ---------------------------------------------------------------------------
__global__ __launch_bounds__(256, 2) void simexp_kernel() {
    __shared__ float As[16][128];
    __shared__ float Bs[16][128];

    const int tid = threadIdx.x;
    const int tx = tid & 15;
    const int ty = tid >> 4;
    const int rowBase = blockIdx.y * 128;
    const int colBase = blockIdx.x * 128;

    const float* __restrict__ A = g_f + (size_t)rowBase * DIMK;
    const float* __restrict__ Bt = g_f + (size_t)colBase * DIMK;

    unsigned long long acc[8][4];
    #pragma unroll
    for (int i = 0; i < 8; i++)
        #pragma unroll
        for (int j = 0; j < 4; j++) acc[i][j] = 0ull;   // bit pattern of (0.f, 0.f)

    // Load mapping: each thread loads 2 float4 per tile for A and B.
    const int lcol = tid & 127;   // tile-local row (A) / col (B)
    const int lk4 = tid >> 7;     // 0..1; second load uses lk4+2

    for (int kt = 0; kt < DIMK; kt += 16) {
        __syncthreads();
        {
            const float* pa = A + (size_t)lcol * DIMK + kt;
            float4 a0 = *reinterpret_cast<const float4*>(pa + lk4 * 4);
            float4 a1 = *reinterpret_cast<const float4*>(pa + (lk4 + 2) * 4);
            As[lk4 * 4 + 0][lcol] = a0.x; As[lk4 * 4 + 1][lcol] = a0.y;
            As[lk4 * 4 + 2][lcol] = a0.z; As[lk4 * 4 + 3][lcol] = a0.w;
            As[(lk4 + 2) * 4 + 0][lcol] = a1.x; As[(lk4 + 2) * 4 + 1][lcol] = a1.y;
            As[(lk4 + 2) * 4 + 2][lcol] = a1.z; As[(lk4 + 2) * 4 + 3][lcol] = a1.w;

            const float* pb = Bt + (size_t)lcol * DIMK + kt;
            float4 b0 = *reinterpret_cast<const float4*>(pb + lk4 * 4);
            float4 b1 = *reinterpret_cast<const float4*>(pb + (lk4 + 2) * 4);
            Bs[lk4 * 4 + 0][lcol] = b0.x; Bs[lk4 * 4 + 1][lcol] = b0.y;
            Bs[lk4 * 4 + 2][lcol] = b0.z; Bs[lk4 * 4 + 3][lcol] = b0.w;
            Bs[(lk4 + 2) * 4 + 0][lcol] = b1.x; Bs[(lk4 + 2) * 4 + 1][lcol] = b1.y;
            Bs[(lk4 + 2) * 4 + 2][lcol] = b1.z; Bs[(lk4 + 2) * 4 + 3][lcol] = b1.w;
        }
        __syncthreads();

        #pragma unroll
        for (int k = 0; k < 16; k++) {
            unsigned long long ad[8], bp[4];
            #pragma unroll
            for (int i = 0; i < 8; i++) {
                float a = As[k][ty * 8 + i];
                ad[i] = pack2(a, a);
            }
            #pragma unroll
            for (int j = 0; j < 4; j++) {
                float b0 = Bs[k][tx + (2 * j) * 16];
                float b1 = Bs[k][tx + (2 * j + 1) * 16];
                bp[j] = pack2(b0, b1);
            }
            #pragma unroll
            for (int i = 0; i < 8; i++)
                #pragma unroll
                for (int j = 0; j < 4; j++)
                    fma2(acc[i][j], ad[i], bp[j]);
        }
    }

    // Epilogue: exp, mask diagonal, reduce across the 16 lanes sharing ty,
    // one atomicAdd per (row, CTA).
    #pragma unroll
    for (int i = 0; i < 8; i++) {
        int r = rowBase + ty * 8 + i;
        float s = 0.f;
        #pragma unroll
        for (int j = 0; j < 4; j++) {
            float lo, hi;
            unpack2(acc[i][j], lo, hi);
            int c0 = colBase + tx + (2 * j) * 16;
            int c1 = colBase + tx + (2 * j + 1) * 16;
            if (r != c0) s += __expf(lo * INV_T);
            if (r != c1) s += __expf(hi * INV_T);
        }
        #pragma unroll
        for (int m = 8; m; m >>= 1) s += __shfl_xor_sync(0xffffffffu, s, m);
        if (tx == 0) atomicAdd(&g_sumexp[r], s);
    }
}

// ---------------------------------------------------------------------------
// Kernel C: positive-pair dot + final loss. One warp per row.
// loss_i = log(sumexp_i) - dot(f_i, f_pos(i)) / T ; mean via atomicAdd.
// ---------------------------------------------------------------------------
__global__ void loss_kernel(float* __restrict__ out) {
    int warp = threadIdx.x >> 5;
    int lane = threadIdx.x & 31;
    int r = blockIdx.x * 8 + warp;
    int pr = (r < HALF_N) ? r + HALF_N : r - HALF_N;

    const float4* fr = reinterpret_cast<const float4*>(g_f + (size_t)r * DIMK);
    const float4* fp = reinterpret_cast<const float4*>(g_f + (size_t)pr * DIMK);
    float dot = 0.f;
    #pragma unroll
    for (int i = 0; i < 8; i++) {
        float4 a = fr[lane + i * 32];
        float4 b = fp[lane + i * 32];
        dot += a.x * b.x + a.y * b.y + a.z * b.z + a.w * b.w;
    }
    #pragma unroll
    for (int m = 16; m; m >>= 1) dot += __shfl_xor_sync(0xffffffffu, dot, m);

    if (lane == 0) {
        float loss = logf(g_sumexp[r]) - dot * INV_T;
        atomicAdd(out, loss * (1.0f / N_ROWS));
    }
}

// ---------------------------------------------------------------------------
extern "C" void kernel_launch(void* const* d_in, const int* in_sizes, int n_in,
                              void* d_out, int out_size) {
    const float* features = (const float*)d_in[0];
    float* out = (float*)d_out;

    norm_kernel<<<N_ROWS, 256>>>(features, out);

    dim3 grid(N_ROWS / 128, N_ROWS / 128);
    simexp_kernel<<<grid, 256>>>();

    loss_kernel<<<N_ROWS / 8, 256>>>(out);
}

// round 3
// speedup vs baseline: 15.0920x; 15.0920x over previous
#include <cuda_runtime.h>
#include <cuda_bf16.h>
#include <cstdint>

// Problem constants
#define N_ROWS 8192
#define DIMK   1024
#define HALF_N 4096
#define INV_T  (1.0f / 0.07f)

#define TILE 128          // CTA tile: 128 x 128
#define KCH  32           // K chunk per mainloop iter
#define NBLK (N_ROWS / TILE)            // 64
#define NTRI (NBLK * (NBLK + 1) / 2)    // 2080 upper-triangular tiles

// Scratch (allocation-free rule: __device__ globals)
__device__ float         g_f[N_ROWS * DIMK];    // normalized fp32 (pos dot)
__device__ __nv_bfloat16 g_fb[N_ROWS * DIMK];   // normalized bf16 (GEMM operands)
__device__ float         g_sumexp[N_ROWS];

// ---------------------------------------------------------------------------
__device__ __forceinline__ uint32_t smem_u32(const void* p) {
    uint32_t a;
    asm("{ .reg .u64 t; cvta.to.shared.u64 t, %1; cvt.u32.u64 %0, t; }" : "=r"(a) : "l"(p));
    return a;
}
#define CP16(dst, src) \
    asm volatile("cp.async.cg.shared.global [%0], [%1], 16;" :: "r"(dst), "l"(src) : "memory")
#define CP_COMMIT() asm volatile("cp.async.commit_group;" ::: "memory")
#define CP_WAIT(n)  asm volatile("cp.async.wait_group %0;" :: "n"(n) : "memory")

#define LDSM_X4(r0, r1, r2, r3, addr)                                        \
    asm volatile("ldmatrix.sync.aligned.m8n8.x4.shared.b16 {%0,%1,%2,%3}, [%4];" \
        : "=r"(r0), "=r"(r1), "=r"(r2), "=r"(r3) : "r"(addr))

#define MMA_BF16(d, a, b)                                                    \
    asm volatile("mma.sync.aligned.m16n8k16.row.col.f32.bf16.bf16.f32 "      \
        "{%0,%1,%2,%3}, {%4,%5,%6,%7}, {%8,%9}, {%0,%1,%2,%3};"              \
        : "+f"((d)[0]), "+f"((d)[1]), "+f"((d)[2]), "+f"((d)[3])             \
        : "r"((a)[0]), "r"((a)[1]), "r"((a)[2]), "r"((a)[3]),                \
          "r"((b)[0]), "r"((b)[1]))

// Swizzled smem byte offset for (row, kc16) in a [128 x 64B] tile.
// kc ^ ((row>>1)&3) makes every 8-lane ldmatrix phase conflict-free.
__device__ __forceinline__ uint32_t sw_off(int row, int kc) {
    return (uint32_t)(row * 64 + ((kc ^ ((row >> 1) & 3)) << 4));
}

// ---------------------------------------------------------------------------
// Kernel A: normalize rows -> g_f (fp32) + g_fb (bf16); zero accumulators.
// ---------------------------------------------------------------------------
__global__ void norm_kernel(const float* __restrict__ in, float* __restrict__ out) {
    int r = blockIdx.x;
    int t = threadIdx.x;
    const float4* src = reinterpret_cast<const float4*>(in + (size_t)r * DIMK);
    float4 v = src[t];
    float ss = v.x * v.x + v.y * v.y + v.z * v.z + v.w * v.w;
    #pragma unroll
    for (int m = 16; m; m >>= 1) ss += __shfl_xor_sync(0xffffffffu, ss, m);

    __shared__ float warpsum[8];
    if ((t & 31) == 0) warpsum[t >> 5] = ss;
    __syncthreads();
    __shared__ float s_inv;
    if (t == 0) {
        float s = 0.f;
        #pragma unroll
        for (int i = 0; i < 8; i++) s += warpsum[i];
        s_inv = 1.0f / sqrtf(s);
    }
    __syncthreads();
    float inv = s_inv;
    float4 o = make_float4(v.x * inv, v.y * inv, v.z * inv, v.w * inv);
    reinterpret_cast<float4*>(g_f + (size_t)r * DIMK)[t] = o;

    __nv_bfloat162 b0 = __floats2bfloat162_rn(o.x, o.y);
    __nv_bfloat162 b1 = __floats2bfloat162_rn(o.z, o.w);
    uint2 packed = make_uint2(*reinterpret_cast<uint32_t*>(&b0),
                              *reinterpret_cast<uint32_t*>(&b1));
    reinterpret_cast<uint2*>(g_fb + (size_t)r * DIMK)[t] = packed;

    if (t == 0) g_sumexp[r] = 0.0f;
    if (r == 0 && t == 0) out[0] = 0.0f;   // d_out poisoned; zero before atomics
}

// ---------------------------------------------------------------------------
// Kernel B: bf16 mma.sync GEMM over upper-triangular tiles with fused
// exp + diagonal mask + row/col partial sums (symmetry).
// 256 threads = 8 warps arranged 4(M) x 2(N); warp tile 32 x 64.
// ---------------------------------------------------------------------------
__global__ __launch_bounds__(256, 2) void simexp_kernel() {
    __shared__ __align__(16) char sA[2][TILE * 64];   // [128 rows][32 k] bf16
    __shared__ __align__(16) char sB[2][TILE * 64];
    __shared__ float s_rowsum[TILE];
    __shared__ float s_colsum[TILE];

    const int tid = threadIdx.x;
    const int lane = tid & 31;
    const int wid = tid >> 5;
    const int warp_m = wid & 3;       // 0..3
    const int warp_n = wid >> 2;      // 0..1

    // linear tile id -> (bi, bj), bi <= bj
    int t = blockIdx.x;
    int bi = (int)(64.5f - sqrtf(64.5f * 64.5f - 2.0f * (float)t));
    if (bi < 0) bi = 0;
    if (bi >= NBLK) bi = NBLK - 1;
    #pragma unroll 1
    while (bi + 1 <= NBLK - 1 && (bi + 1) * NBLK - ((bi + 1) * bi) / 2 <= t) bi++;
    #pragma unroll 1
    while (bi > 0 && bi * NBLK - (bi * (bi - 1)) / 2 > t) bi--;
    const int bj = bi + (t - (bi * NBLK - (bi * (bi - 1)) / 2));
    const int rowBase = bi * TILE;
    const int colBase = bj * TILE;
    const bool diag = (bi == bj);

    if (tid < TILE) { s_rowsum[tid] = 0.f; s_colsum[tid] = 0.f; }

    const uint32_t sAu[2] = { smem_u32(sA[0]), smem_u32(sA[1]) };
    const uint32_t sBu[2] = { smem_u32(sB[0]), smem_u32(sB[1]) };

    float acc[2][8][4];
    #pragma unroll
    for (int mi = 0; mi < 2; mi++)
        #pragma unroll
        for (int ni = 0; ni < 8; ni++)
            #pragma unroll
            for (int k = 0; k < 4; k++) acc[mi][ni][k] = 0.f;

    // ---- tile loader: 1024 x 16B chunks (A 512, B 512) / 256 threads ----
    auto load_tile = [&](int stage, int k0) {
        #pragma unroll
        for (int i = 0; i < 2; i++) {
            int c = tid + i * 256;                 // A chunk 0..511
            int row = c >> 2, kc = c & 3;
            CP16(sAu[stage] + sw_off(row, kc),
                 g_fb + (size_t)(rowBase + row) * DIMK + k0 + kc * 8);
        }
        #pragma unroll
        for (int i = 0; i < 2; i++) {
            int c = tid + i * 256;                 // B chunk 0..511
            int row = c >> 2, kc = c & 3;
            CP16(sBu[stage] + sw_off(row, kc),
                 g_fb + (size_t)(colBase + row) * DIMK + k0 + kc * 8);
        }
        CP_COMMIT();
    };

    load_tile(0, 0);

    const int KITERS = DIMK / KCH;    // 32
    #pragma unroll 1
    for (int it = 0; it < KITERS; it++) {
        const int stage = it & 1;
        if (it + 1 < KITERS) {
            load_tile(stage ^ 1, (it + 1) * KCH);
            CP_WAIT(1);
        } else {
            CP_WAIT(0);
        }
        __syncthreads();

        const uint32_t a_base = sAu[stage];
        const uint32_t b_base = sBu[stage];

        #pragma unroll
        for (int ks = 0; ks < 2; ks++) {
            uint32_t a[2][4];
            #pragma unroll
            for (int mi = 0; mi < 2; mi++) {
                int row = warp_m * 32 + mi * 16 + (lane & 15);
                int kc = ks * 2 + (lane >> 4);
                LDSM_X4(a[mi][0], a[mi][1], a[mi][2], a[mi][3],
                        a_base + sw_off(row, kc));
            }
            uint32_t b[8][2];
            #pragma unroll
            for (int nq = 0; nq < 4; nq++) {
                int nrow = warp_n * 64 + nq * 16 + (((lane >> 4) << 3) | (lane & 7));
                int kc = ks * 2 + ((lane >> 3) & 1);
                uint32_t t0, t1, t2, t3;
                LDSM_X4(t0, t1, t2, t3, b_base + sw_off(nrow, kc));
                b[nq * 2][0] = t0; b[nq * 2][1] = t1;
                b[nq * 2 + 1][0] = t2; b[nq * 2 + 1][1] = t3;
            }
            #pragma unroll
            for (int mi = 0; mi < 2; mi++)
                #pragma unroll
                for (int ni = 0; ni < 8; ni++)
                    MMA_BF16(acc[mi][ni], a[mi], b[ni]);
        }
        __syncthreads();
    }

    // ---- epilogue: exp, diagonal mask, row/col partial sums ----
    const int g = lane >> 2;      // row group 0..7
    const int q4 = lane & 3;      // col pair 0..3

    float csumE[8], csumO[8];
    #pragma unroll
    for (int ni = 0; ni < 8; ni++) { csumE[ni] = 0.f; csumO[ni] = 0.f; }

    #pragma unroll
    for (int mi = 0; mi < 2; mi++) {
        float rs0 = 0.f, rs1 = 0.f;
        const int ra = rowBase + warp_m * 32 + mi * 16 + g;
        const int rb = ra + 8;
        #pragma unroll
        for (int ni = 0; ni < 8; ni++) {
            const int cb = colBase + warp_n * 64 + ni * 8 + q4 * 2;
            float e0 = __expf(acc[mi][ni][0] * INV_T);
            float e1 = __expf(acc[mi][ni][1] * INV_T);
            float e2 = __expf(acc[mi][ni][2] * INV_T);
            float e3 = __expf(acc[mi][ni][3] * INV_T);
            if (ra == cb)     e0 = 0.f;
            if (ra == cb + 1) e1 = 0.f;
            if (rb == cb)     e2 = 0.f;
            if (rb == cb + 1) e3 = 0.f;
            rs0 += e0 + e1;
            rs1 += e2 + e3;
            csumE[ni] += e0 + e2;
            csumO[ni] += e1 + e3;
        }
        rs0 += __shfl_xor_sync(0xffffffffu, rs0, 1);
        rs0 += __shfl_xor_sync(0xffffffffu, rs0, 2);
        rs1 += __shfl_xor_sync(0xffffffffu, rs1, 1);
        rs1 += __shfl_xor_sync(0xffffffffu, rs1, 2);
        if (q4 == 0) {
            atomicAdd(&s_rowsum[warp_m * 32 + mi * 16 + g], rs0);
            atomicAdd(&s_rowsum[warp_m * 32 + mi * 16 + 8 + g], rs1);
        }
    }

    #pragma unroll
    for (int ni = 0; ni < 8; ni++) {
        float vE = csumE[ni], vO = csumO[ni];
        #pragma unroll
        for (int m = 4; m <= 16; m <<= 1) {
            vE += __shfl_xor_sync(0xffffffffu, vE, m);
            vO += __shfl_xor_sync(0xffffffffu, vO, m);
        }
        if (lane < 4) {
            atomicAdd(&s_colsum[warp_n * 64 + ni * 8 + q4 * 2], vE);
            atomicAdd(&s_colsum[warp_n * 64 + ni * 8 + q4 * 2 + 1], vO);
        }
    }

    __syncthreads();
    if (tid < TILE) {
        atomicAdd(&g_sumexp[rowBase + tid], s_rowsum[tid]);
        if (!diag)
            atomicAdd(&g_sumexp[colBase + tid], s_colsum[tid]);
    }
}

// ---------------------------------------------------------------------------
// Kernel C: positive-pair dot (fp32) + final loss. One warp per row.
// ---------------------------------------------------------------------------
__global__ void loss_kernel(float* __restrict__ out) {
    int warp = threadIdx.x >> 5;
    int lane = threadIdx.x & 31;
    int r = blockIdx.x * 8 + warp;
    int pr = (r < HALF_N) ? r + HALF_N : r - HALF_N;

    const float4* fr = reinterpret_cast<const float4*>(g_f + (size_t)r * DIMK);
    const float4* fp = reinterpret_cast<const float4*>(g_f + (size_t)pr * DIMK);
    float dot = 0.f;
    #pragma unroll
    for (int i = 0; i < 8; i++) {
        float4 a = fr[lane + i * 32];
        float4 b = fp[lane + i * 32];
        dot += a.x * b.x + a.y * b.y + a.z * b.z + a.w * b.w;
    }
    #pragma unroll
    for (int m = 16; m; m >>= 1) dot += __shfl_xor_sync(0xffffffffu, dot, m);

    if (lane == 0) {
        float loss = logf(g_sumexp[r]) - dot * INV_T;
        atomicAdd(out, loss * (1.0f / N_ROWS));
    }
}

// ---------------------------------------------------------------------------
extern "C" void kernel_launch(void* const* d_in, const int* in_sizes, int n_in,
                              void* d_out, int out_size) {
    const float* features = (const float*)d_in[0];
    float* out = (float*)d_out;

    norm_kernel<<<N_ROWS, 256>>>(features, out);
    simexp_kernel<<<NTRI, 256>>>();
    loss_kernel<<<N_ROWS / 8, 256>>>(out);
}

// round 4
// speedup vs baseline: 17.3138x; 1.1472x over previous
#include <cuda_runtime.h>
#include <cuda_bf16.h>
#include <cstdint>

// Problem constants
#define N_ROWS 8192
#define DIMK   1024
#define HALF_N 4096
#define INV_T  (1.0f / 0.07f)

#define TILE 128          // CTA tile: 128 x 128
#define KCH  64           // K chunk per mainloop iter
#define KITERS (DIMK / KCH)             // 16
#define NBLK (N_ROWS / TILE)            // 64
#define NTRI (NBLK * (NBLK + 1) / 2)    // 2080 upper-triangular tiles

#define STAGE_BYTES (2 * TILE * 128)    // A(16KB) + B(16KB) per stage
#define SMEM_DYN (3 * STAGE_BYTES)      // 96 KB

// Scratch (allocation-free rule: __device__ globals)
__device__ __nv_bfloat16 g_fb[N_ROWS * DIMK];   // normalized bf16 (GEMM operands)
__device__ float         g_sumexp[N_ROWS];
__device__ float         g_pos[N_ROWS];         // positive-pair dot (unscaled)

// ---------------------------------------------------------------------------
__device__ __forceinline__ uint32_t smem_u32(const void* p) {
    uint32_t a;
    asm("{ .reg .u64 t; cvta.to.shared.u64 t, %1; cvt.u32.u64 %0, t; }" : "=r"(a) : "l"(p));
    return a;
}
#define CP16(dst, src) \
    asm volatile("cp.async.cg.shared.global [%0], [%1], 16;" :: "r"(dst), "l"(src) : "memory")
#define CP_COMMIT() asm volatile("cp.async.commit_group;" ::: "memory")
#define CP_WAIT(n)  asm volatile("cp.async.wait_group %0;" :: "n"(n) : "memory")

#define LDSM_X4(r0, r1, r2, r3, addr)                                        \
    asm volatile("ldmatrix.sync.aligned.m8n8.x4.shared.b16 {%0,%1,%2,%3}, [%4];" \
        : "=r"(r0), "=r"(r1), "=r"(r2), "=r"(r3) : "r"(addr))

#define MMA_BF16(d, a, b)                                                    \
    asm volatile("mma.sync.aligned.m16n8k16.row.col.f32.bf16.bf16.f32 "      \
        "{%0,%1,%2,%3}, {%4,%5,%6,%7}, {%8,%9}, {%0,%1,%2,%3};"              \
        : "+f"((d)[0]), "+f"((d)[1]), "+f"((d)[2]), "+f"((d)[3])             \
        : "r"((a)[0]), "r"((a)[1]), "r"((a)[2]), "r"((a)[3]),                \
          "r"((b)[0]), "r"((b)[1]))

// Swizzled smem byte offset for (row, kc16) in a [128 rows x 128 B] tile.
// 8 x 16B chunks per row; chunk ^= row&7 (SW128 pattern) -> conflict-free
// for both cp.async stores and every 8-lane ldmatrix phase.
__device__ __forceinline__ uint32_t sw_off(int row, int kc) {
    return (uint32_t)(row * 128 + ((kc ^ (row & 7)) << 4));
}

// ---------------------------------------------------------------------------
// Kernel A: normalize rows -> g_fb (bf16); zero accumulators + out.
// ---------------------------------------------------------------------------
__global__ void norm_kernel(const float* __restrict__ in, float* __restrict__ out) {
    int r = blockIdx.x;
    int t = threadIdx.x;
    const float4* src = reinterpret_cast<const float4*>(in + (size_t)r * DIMK);
    float4 v = src[t];
    float ss = v.x * v.x + v.y * v.y + v.z * v.z + v.w * v.w;
    #pragma unroll
    for (int m = 16; m; m >>= 1) ss += __shfl_xor_sync(0xffffffffu, ss, m);

    __shared__ float warpsum[8];
    if ((t & 31) == 0) warpsum[t >> 5] = ss;
    __syncthreads();
    __shared__ float s_inv;
    if (t == 0) {
        float s = 0.f;
        #pragma unroll
        for (int i = 0; i < 8; i++) s += warpsum[i];
        s_inv = 1.0f / sqrtf(s);
    }
    __syncthreads();
    float inv = s_inv;
    __nv_bfloat162 b0 = __floats2bfloat162_rn(v.x * inv, v.y * inv);
    __nv_bfloat162 b1 = __floats2bfloat162_rn(v.z * inv, v.w * inv);
    uint2 packed = make_uint2(*reinterpret_cast<uint32_t*>(&b0),
                              *reinterpret_cast<uint32_t*>(&b1));
    reinterpret_cast<uint2*>(g_fb + (size_t)r * DIMK)[t] = packed;

    if (t == 0) g_sumexp[r] = 0.0f;
    if (r == 0 && t == 0) out[0] = 0.0f;   // d_out poisoned; zero before atomics
}

// ---------------------------------------------------------------------------
// Kernel B: bf16 mma.sync GEMM over upper-triangular tiles with fused
// exp + diagonal mask + row/col partial sums (symmetry) + pos extraction.
// 256 threads = 8 warps arranged 4(M) x 2(N); warp tile 32 x 64.
// 3-stage cp.async pipeline, one __syncthreads per K-iter.
// ---------------------------------------------------------------------------
__global__ __launch_bounds__(256, 2) void simexp_kernel() {
    extern __shared__ __align__(16) char dsmem[];
    __shared__ float s_rowsum[TILE];
    __shared__ float s_colsum[TILE];

    const int tid = threadIdx.x;
    const int lane = tid & 31;
    const int wid = tid >> 5;
    const int warp_m = wid & 3;       // 0..3
    const int warp_n = wid >> 2;      // 0..1

    // linear tile id -> (bi, bj), bi <= bj
    int t = blockIdx.x;
    int bi = (int)(64.5f - sqrtf(64.5f * 64.5f - 2.0f * (float)t));
    if (bi < 0) bi = 0;
    if (bi >= NBLK) bi = NBLK - 1;
    #pragma unroll 1
    while (bi + 1 <= NBLK - 1 && (bi + 1) * NBLK - ((bi + 1) * bi) / 2 <= t) bi++;
    #pragma unroll 1
    while (bi > 0 && bi * NBLK - (bi * (bi - 1)) / 2 > t) bi--;
    const int bj = bi + (t - (bi * NBLK - (bi * (bi - 1)) / 2));
    const int rowBase = bi * TILE;
    const int colBase = bj * TILE;
    const bool diag = (bi == bj);
    const bool posTile = (colBase - rowBase == HALF_N);

    if (tid < TILE) { s_rowsum[tid] = 0.f; s_colsum[tid] = 0.f; }

    uint32_t sbase = smem_u32(dsmem);
    uint32_t sAu[3], sBu[3];
    #pragma unroll
    for (int s = 0; s < 3; s++) {
        sAu[s] = sbase + s * STAGE_BYTES;
        sBu[s] = sAu[s] + TILE * 128;
    }

    float acc[2][8][4];
    #pragma unroll
    for (int mi = 0; mi < 2; mi++)
        #pragma unroll
        for (int ni = 0; ni < 8; ni++)
            #pragma unroll
            for (int k = 0; k < 4; k++) acc[mi][ni][k] = 0.f;

    // ---- tile loader: per matrix 1024 x 16B chunks / 256 threads = 4 each ----
    auto load_tile = [&](int stage, int k0) {
        #pragma unroll
        for (int i = 0; i < 4; i++) {
            int c = tid + i * 256;                 // 0..1023
            int row = c >> 3, kc = c & 7;
            CP16(sAu[stage] + sw_off(row, kc),
                 g_fb + (size_t)(rowBase + row) * DIMK + k0 + kc * 8);
        }
        #pragma unroll
        for (int i = 0; i < 4; i++) {
            int c = tid + i * 256;
            int row = c >> 3, kc = c & 7;
            CP16(sBu[stage] + sw_off(row, kc),
                 g_fb + (size_t)(colBase + row) * DIMK + k0 + kc * 8);
        }
        CP_COMMIT();
    };

    // Prologue: tiles 0 and 1
    load_tile(0, 0);
    load_tile(1, KCH);

    #pragma unroll 1
    for (int it = 0; it < KITERS; it++) {
        CP_WAIT(1);          // this thread's copies of tile `it` arrived
        __syncthreads();     // all threads' copies visible; compute(it-1) done

        // Prefetch tile it+2 into stage (it+2)%3 == (it-1)%3 (now free)
        if (it + 2 < KITERS) load_tile((it + 2) % 3, (it + 2) * KCH);
        else CP_COMMIT();    // keep group arithmetic uniform

        const uint32_t a_base = sAu[it % 3];
        const uint32_t b_base = sBu[it % 3];

        #pragma unroll
        for (int ks = 0; ks < 4; ks++) {
            uint32_t a[2][4];
            #pragma unroll
            for (int mi = 0; mi < 2; mi++) {
                int row = warp_m * 32 + mi * 16 + (lane & 15);
                int kc = ks * 2 + (lane >> 4);
                LDSM_X4(a[mi][0], a[mi][1], a[mi][2], a[mi][3],
                        a_base + sw_off(row, kc));
            }
            uint32_t b[8][2];
            #pragma unroll
            for (int nq = 0; nq < 4; nq++) {
                int nrow = warp_n * 64 + nq * 16 + (((lane >> 4) << 3) | (lane & 7));
                int kc = ks * 2 + ((lane >> 3) & 1);
                uint32_t t0, t1, t2, t3;
                LDSM_X4(t0, t1, t2, t3, b_base + sw_off(nrow, kc));
                b[nq * 2][0] = t0; b[nq * 2][1] = t1;
                b[nq * 2 + 1][0] = t2; b[nq * 2 + 1][1] = t3;
            }
            #pragma unroll
            for (int mi = 0; mi < 2; mi++)
                #pragma unroll
                for (int ni = 0; ni < 8; ni++)
                    MMA_BF16(acc[mi][ni], a[mi], b[ni]);
        }
    }
    __syncthreads();   // protect smem sums below vs last compute

    // ---- epilogue: pos extraction, exp, diagonal mask, row/col sums ----
    const int g = lane >> 2;      // row group 0..7
    const int q4 = lane & 3;      // col pair 0..3

    float csumE[8], csumO[8];
    #pragma unroll
    for (int ni = 0; ni < 8; ni++) { csumE[ni] = 0.f; csumO[ni] = 0.f; }

    #pragma unroll
    for (int mi = 0; mi < 2; mi++) {
        float rs0 = 0.f, rs1 = 0.f;
        const int ra = rowBase + warp_m * 32 + mi * 16 + g;
        const int rb = ra + 8;
        #pragma unroll
        for (int ni = 0; ni < 8; ni++) {
            const int cb = colBase + warp_n * 64 + ni * 8 + q4 * 2;
            const float v0 = acc[mi][ni][0], v1 = acc[mi][ni][1];
            const float v2 = acc[mi][ni][2], v3 = acc[mi][ni][3];

            if (posTile) {   // local diagonal of the (bi, bi+32) tile = pos dot
                if (cb     == ra + HALF_N) { g_pos[ra] = v0; g_pos[cb]     = v0; }
                if (cb + 1 == ra + HALF_N) { g_pos[ra] = v1; g_pos[cb + 1] = v1; }
                if (cb     == rb + HALF_N) { g_pos[rb] = v2; g_pos[cb]     = v2; }
                if (cb + 1 == rb + HALF_N) { g_pos[rb] = v3; g_pos[cb + 1] = v3; }
            }

            float e0 = __expf(v0 * INV_T);
            float e1 = __expf(v1 * INV_T);
            float e2 = __expf(v2 * INV_T);
            float e3 = __expf(v3 * INV_T);
            if (ra == cb)     e0 = 0.f;
            if (ra == cb + 1) e1 = 0.f;
            if (rb == cb)     e2 = 0.f;
            if (rb == cb + 1) e3 = 0.f;
            rs0 += e0 + e1;
            rs1 += e2 + e3;
            csumE[ni] += e0 + e2;
            csumO[ni] += e1 + e3;
        }
        rs0 += __shfl_xor_sync(0xffffffffu, rs0, 1);
        rs0 += __shfl_xor_sync(0xffffffffu, rs0, 2);
        rs1 += __shfl_xor_sync(0xffffffffu, rs1, 1);
        rs1 += __shfl_xor_sync(0xffffffffu, rs1, 2);
        if (q4 == 0) {
            atomicAdd(&s_rowsum[warp_m * 32 + mi * 16 + g], rs0);
            atomicAdd(&s_rowsum[warp_m * 32 + mi * 16 + 8 + g], rs1);
        }
    }

    #pragma unroll
    for (int ni = 0; ni < 8; ni++) {
        float vE = csumE[ni], vO = csumO[ni];
        #pragma unroll
        for (int m = 4; m <= 16; m <<= 1) {
            vE += __shfl_xor_sync(0xffffffffu, vE, m);
            vO += __shfl_xor_sync(0xffffffffu, vO, m);
        }
        if (lane < 4) {
            atomicAdd(&s_colsum[warp_n * 64 + ni * 8 + q4 * 2], vE);
            atomicAdd(&s_colsum[warp_n * 64 + ni * 8 + q4 * 2 + 1], vO);
        }
    }

    __syncthreads();
    if (tid < TILE) {
        atomicAdd(&g_sumexp[rowBase + tid], s_rowsum[tid]);
        if (!diag)
            atomicAdd(&g_sumexp[colBase + tid], s_colsum[tid]);
    }
}

// ---------------------------------------------------------------------------
// Kernel C: finalize. loss_i = log(sumexp_i) - pos_i / T ; mean via atomics.
// ---------------------------------------------------------------------------
__global__ void finalize_kernel(float* __restrict__ out) {
    int i = blockIdx.x * 256 + threadIdx.x;
    float loss = logf(g_sumexp[i]) - g_pos[i] * INV_T;

    #pragma unroll
    for (int m = 16; m; m >>= 1) loss += __shfl_xor_sync(0xffffffffu, loss, m);
    __shared__ float ws[8];
    if ((threadIdx.x & 31) == 0) ws[threadIdx.x >> 5] = loss;
    __syncthreads();
    if (threadIdx.x == 0) {
        float s = 0.f;
        #pragma unroll
        for (int k = 0; k < 8; k++) s += ws[k];
        atomicAdd(out, s * (1.0f / N_ROWS));
    }
}

// ---------------------------------------------------------------------------
extern "C" void kernel_launch(void* const* d_in, const int* in_sizes, int n_in,
                              void* d_out, int out_size) {
    const float* features = (const float*)d_in[0];
    float* out = (float*)d_out;

    static bool configured = false;
    if (!configured) {
        cudaFuncSetAttribute(simexp_kernel,
                             cudaFuncAttributeMaxDynamicSharedMemorySize, SMEM_DYN);
        configured = true;
    }

    norm_kernel<<<N_ROWS, 256>>>(features, out);
    simexp_kernel<<<NTRI, 256, SMEM_DYN>>>();
    finalize_kernel<<<N_ROWS / 256, 256>>>(out);
}